// round 15
// baseline (speedup 1.0000x reference)
#include <cuda_runtime.h>
#include <cuda_bf16.h>
#include <cstdint>

// ---------------- problem constants ----------------
#define Bb   64
#define Tt   512
#define Ee   256
#define Hh   256
#define G4   1024          // 4*H
#define Oo   2

// ---------------- scratch (device globals: no runtime alloc) ----------------
__device__ float g_xproj[(size_t)Tt * Bb * G4];   // [t][b][gate] fp32, 128MB
__device__ float g_hf[Bb * Hh];                   // final forward hidden

__device__ __forceinline__ float sigm(float x) {
    return __fdividef(1.0f, 1.0f + __expf(-x));
}
__device__ __forceinline__ float tanh_mufu(float x) {
    float r;
    asm("tanh.approx.f32 %0, %1;" : "=f"(r) : "f"(x));
    return r;
}
__device__ __forceinline__ float sigm_mufu(float x) {
    return fmaf(tanh_mufu(0.5f * x), 0.5f, 0.5f);
}

// =====================================================================
// Kernel 1: xproj = emb[x] @ W_ih_f^T + bias via mma.sync tf32
// (round-11 exact: 185.6us)
// =====================================================================
#define XBM 128
#define XBN 128
#define XBK 32
#define XPAD 136
#define XCHW (XBK * XPAD)
#define XBUFW (2 * XCHW)
#define XBIAS_OFF (2 * XBUFW)
#define XSMEM_BYTES ((XBIAS_OFF + XBN) * 4)

__device__ __forceinline__ uint32_t f2tf32(float v) {
    uint32_t r;
    asm("cvt.rna.tf32.f32 %0, %1;" : "=r"(r) : "f"(v));
    return r;
}

__device__ __forceinline__ void mma_tf32(
    float& d0, float& d1, float& d2, float& d3,
    uint32_t a0, uint32_t a1, uint32_t a2, uint32_t a3,
    uint32_t b0, uint32_t b1)
{
    asm volatile(
        "mma.sync.aligned.m16n8k8.row.col.f32.tf32.tf32.f32 "
        "{%0,%1,%2,%3}, {%4,%5,%6,%7}, {%8,%9}, {%0,%1,%2,%3};"
        : "+f"(d0), "+f"(d1), "+f"(d2), "+f"(d3)
        : "r"(a0), "r"(a1), "r"(a2), "r"(a3), "r"(b0), "r"(b1));
}

__global__ void __launch_bounds__(256, 1) xproj_mma_kernel(
    const int* __restrict__ x,
    const float* __restrict__ emb,
    const float* __restrict__ wih,
    const float* __restrict__ bih,
    const float* __restrict__ bhh)
{
    extern __shared__ __align__(16) float s[];
    const int tid  = threadIdx.x;
    const int wid  = tid >> 5;
    const int lane = tid & 31;
    const int g    = lane >> 2;
    const int c    = lane & 3;
    const int bm   = blockIdx.x;
    const int bn   = blockIdx.y;
    const int warp_m = (wid >> 1) * 32;
    const int warp_n = (wid & 1) * 64;

    const int r  = tid >> 1;
    const int kq = tid & 1;
    const int m  = bm * XBM + r;
    const int tok = x[(m & 63) * Tt + (m >> 6)];
    const float* aptr = emb + (size_t)tok * Ee + kq * 16;
    const float* bptr = wih + (size_t)(bn * XBN + r) * Ee + kq * 16;

    if (tid < XBN)
        s[XBIAS_OFF + tid] = bih[bn * XBN + tid] + bhh[bn * XBN + tid];

    float d[2][8][4];
#pragma unroll
    for (int i = 0; i < 2; i++)
#pragma unroll
        for (int n = 0; n < 8; n++)
#pragma unroll
            for (int e = 0; e < 4; e++) d[i][n][e] = 0.0f;

    float4 av[4], bv[4];

#pragma unroll
    for (int i = 0; i < 4; i++) {
        av[i] = *(const float4*)(aptr + 4 * i);
        bv[i] = *(const float4*)(bptr + 4 * i);
    }
    {
        uint32_t* sa = (uint32_t*)s;
        uint32_t* sb = (uint32_t*)(s + XCHW);
#pragma unroll
        for (int i = 0; i < 4; i++) {
            const float* ae = (const float*)&av[i];
            const float* be = (const float*)&bv[i];
#pragma unroll
            for (int e = 0; e < 4; e++) {
                int k = kq * 16 + 4 * i + e;
                sa[k * XPAD + r] = f2tf32(ae[e]);
                sb[k * XPAD + r] = f2tf32(be[e]);
            }
        }
    }
    __syncthreads();

    for (int ch = 0; ch < 8; ch++) {
        const int buf = ch & 1, nbuf = buf ^ 1;

        if (ch < 7) {
#pragma unroll
            for (int i = 0; i < 4; i++) {
                av[i] = *(const float4*)(aptr + (ch + 1) * XBK + 4 * i);
                bv[i] = *(const float4*)(bptr + (ch + 1) * XBK + 4 * i);
            }
        }

        const uint32_t* As = (const uint32_t*)(s + buf * XBUFW);
        const uint32_t* Bs = As + XCHW;
#pragma unroll
        for (int ks = 0; ks < 4; ks++) {
            const int kr0 = (ks * 8 + c) * XPAD;
            const int kr1 = (ks * 8 + c + 4) * XPAD;
            uint32_t a[2][4];
#pragma unroll
            for (int m16 = 0; m16 < 2; m16++) {
                const int rr = warp_m + m16 * 16 + g;
                a[m16][0] = As[kr0 + rr];
                a[m16][1] = As[kr0 + rr + 8];
                a[m16][2] = As[kr1 + rr];
                a[m16][3] = As[kr1 + rr + 8];
            }
            uint32_t b[8][2];
#pragma unroll
            for (int i = 0; i < 8; i++) {
                const int nn = warp_n + i * 8 + g;
                b[i][0] = Bs[kr0 + nn];
                b[i][1] = Bs[kr1 + nn];
            }
#pragma unroll
            for (int m16 = 0; m16 < 2; m16++)
#pragma unroll
                for (int i = 0; i < 8; i++)
                    mma_tf32(d[m16][i][0], d[m16][i][1], d[m16][i][2], d[m16][i][3],
                             a[m16][0], a[m16][1], a[m16][2], a[m16][3],
                             b[i][0], b[i][1]);
        }

        if (ch < 7) {
            uint32_t* sa = (uint32_t*)(s + nbuf * XBUFW);
            uint32_t* sb = sa + XCHW;
#pragma unroll
            for (int i = 0; i < 4; i++) {
                const float* ae = (const float*)&av[i];
                const float* be = (const float*)&bv[i];
#pragma unroll
                for (int e = 0; e < 4; e++) {
                    int k = kq * 16 + 4 * i + e;
                    sa[k * XPAD + r] = f2tf32(ae[e]);
                    sb[k * XPAD + r] = f2tf32(be[e]);
                }
            }
            __syncthreads();
        }
    }

    const float* sbias = s + XBIAS_OFF;
#pragma unroll
    for (int m16 = 0; m16 < 2; m16++) {
        const int row0 = bm * XBM + warp_m + m16 * 16 + g;
#pragma unroll
        for (int i = 0; i < 8; i++) {
            const int col_l = warp_n + i * 8 + 2 * c;
            const float bx = sbias[col_l], by = sbias[col_l + 1];
            float2 v0 = make_float2(d[m16][i][0] + bx, d[m16][i][1] + by);
            float2 v1 = make_float2(d[m16][i][2] + bx, d[m16][i][3] + by);
            *(float2*)(g_xproj + (size_t)row0 * G4 + bn * XBN + col_l) = v0;
            *(float2*)(g_xproj + (size_t)(row0 + 8) * G4 + bn * XBN + col_l) = v1;
        }
    }
}

// =====================================================================
// Kernel 2: forward LSTM — CLUSTER-4, TWO INTERLEAVED CHAINS,
// PER-CHAIN named barriers (1+chain) so FMA-warp runahead is bounded
// to one phase per barrier (the r13-proven regime). Staging bar = 3.
// =====================================================================
#define J_STRIDE   272               // bytes per src-CTA h block (256 used + pad)
#define PAR_STRIDE (4 * J_STRIDE)    // 1088
#define CH_STRIDE  (2 * PAR_STRIDE)  // 2176

__device__ __forceinline__ void mbar_wait_cluster(uint32_t mbar, uint32_t parity) {
    asm volatile(
        "{\n\t"
        ".reg .pred P;\n\t"
        "WAIT_%=:\n\t"
        "mbarrier.try_wait.parity.acquire.cluster.shared::cta.b64 P, [%0], %1, 0x989680;\n\t"
        "@P bra DONE_%=;\n\t"
        "bra WAIT_%=;\n\t"
        "DONE_%=:\n\t"
        "}"
        :: "r"(mbar), "r"(parity) : "memory");
}

__global__ void __cluster_dims__(4, 1, 1) __launch_bounds__(512, 1)
lstm_fwd_kernel(const float* __restrict__ whh)
{
    __shared__ __align__(16) unsigned char s_h_raw[2 * CH_STRIDE];  // [chain][par][src][64f]
    __shared__ float s_z[2][256];                     // [chain][row]
    __shared__ __align__(16) float s_xp[2][2][256];   // [chain][parity][gate*64+col]
    __shared__ float s_c[2][64];                      // [chain][col]
    __shared__ __align__(16) float s_out[2][2][64];   // [chain][parity][col]
    __shared__ __align__(8) unsigned long long s_mbar[4];  // [chain*2+parity]

    const int tid  = threadIdx.x;                     // 0..511
    const int j    = blockIdx.x & 3;                  // cluster rank
    const int cl   = blockIdx.x >> 2;                 // batch group (0..31)
    const int row  = tid >> 1;                        // 0..255 (own gate row)
    const int half = tid & 1;                         // k half

    const int grow = ((row >> 6) << 8) + j * 64 + (row & 63);

    // 128 weights (own half of k) as 64 packed f32x2 regs
    unsigned long long w[64];
    {
        const float* wp = whh + (size_t)grow * Hh + half * 128;
#pragma unroll
        for (int q = 0; q < 32; q++) {
            ulonglong2 v = *(const ulonglong2*)(wp + q * 4);
            w[2*q] = v.x; w[2*q+1] = v.y;
        }
    }

    // init
    for (int i = tid; i < 2 * CH_STRIDE / 4; i += 512) ((float*)s_h_raw)[i] = 0.0f;
    if (tid < 128) s_c[tid >> 6][tid & 63] = 0.0f;

    const uint32_t s_h_addr   = (uint32_t)__cvta_generic_to_shared(&s_h_raw[0]);
    const uint32_t s_xp_addr  = (uint32_t)__cvta_generic_to_shared(&s_xp[0][0][0]);
    const uint32_t s_out_addr = (uint32_t)__cvta_generic_to_shared(&s_out[0][0][0]);
    const uint32_t mbar_addr  = (uint32_t)__cvta_generic_to_shared(&s_mbar[0]);

    if (tid == 0) {
#pragma unroll
        for (int b = 0; b < 4; b++)
            asm volatile("mbarrier.init.shared.b64 [%0], 1;"
                         :: "r"(mbar_addr + b * 8) : "memory");
    }

    // prologue prefetch: both chains' t=0 xproj into parity 0
    if (tid < 64) {
#pragma unroll
        for (int chain = 0; chain < 2; chain++) {
#pragma unroll
            for (int gidx = 0; gidx < 4; gidx++) {
                const float* src = g_xproj + ((size_t)0 * Bb + cl * 2 + chain) * G4
                                   + gidx * 256 + j * 64 + tid;
                uint32_t dst = s_xp_addr +
                    (uint32_t)(((chain * 2 + 0) * 256) + gidx * 64 + tid) * 4u;
                asm volatile("cp.async.ca.shared.global [%0], [%1], 4;"
                             :: "r"(dst), "l"(src));
            }
            asm volatile("cp.async.commit_group;" ::: "memory");
        }
    }

    __syncthreads();
    asm volatile("barrier.cluster.arrive.aligned;" ::: "memory");
    asm volatile("barrier.cluster.wait.aligned;"   ::: "memory");

    for (int it = 0; it < 2 * Tt; it++) {
        const int chain = it & 1;
        const int t     = it >> 1;
        const int cur   = t & 1, nxt = cur ^ 1;
        const int cbar  = 1 + chain;          // per-chain named barrier

        // wait for this chain's step-t h (h(0) prefilled locally)
        if (t > 0) {
            int ph = (t & 1) ? ((t >> 1) & 1) : (((t >> 1) + 1) & 1);
            mbar_wait_cluster(mbar_addr + (uint32_t)(chain * 2 + cur) * 8, (uint32_t)ph);
        }
        if (t < Tt - 1 && tid == 0) {
            asm volatile("mbarrier.arrive.expect_tx.shared.b64 _, [%0], %1;"
                         :: "r"(mbar_addr + (uint32_t)(chain * 2 + nxt) * 8), "r"(1024)
                         : "memory");
        }

        // prefetch this chain's next-step xproj (self-prefetch: 4x 4B)
        if (tid < 64) {
            int tn = (t + 1 < Tt) ? t + 1 : (Tt - 1);
#pragma unroll
            for (int gidx = 0; gidx < 4; gidx++) {
                const float* src = g_xproj + ((size_t)tn * Bb + cl * 2 + chain) * G4
                                   + gidx * 256 + j * 64 + tid;
                uint32_t dst = s_xp_addr +
                    (uint32_t)(((chain * 2 + nxt) * 256) + gidx * 64 + tid) * 4u;
                asm volatile("cp.async.ca.shared.global [%0], [%1], 4;"
                             :: "r"(dst), "l"(src));
            }
            asm volatile("cp.async.commit_group;" ::: "memory");
        }

        // ---- Whh @ h for this chain (1 batch) ----
        unsigned long long acc = 0;
        const unsigned char* hb = s_h_raw + chain * CH_STRIDE + cur * PAR_STRIDE
                                  + (half * 2) * J_STRIDE;
#pragma unroll
        for (int sblk = 0; sblk < 2; sblk++) {
#pragma unroll
            for (int q = 0; q < 16; q++) {
                ulonglong2 h2 = *(const ulonglong2*)(hb + sblk * J_STRIDE + q * 16);
                int wi = 2 * (sblk * 16 + q);
                asm("fma.rn.f32x2 %0, %1, %2, %0;" : "+l"(acc) : "l"(w[wi]),   "l"(h2.x));
                asm("fma.rn.f32x2 %0, %1, %2, %0;" : "+l"(acc) : "l"(w[wi+1]), "l"(h2.y));
            }
        }
        float f = __uint_as_float((unsigned)acc) + __uint_as_float((unsigned)(acc >> 32));
        f += __shfl_xor_sync(0xffffffffu, f, 1);
        if (half == 0) s_z[chain][row] = f;

        if (tid < 64) {
            asm volatile("bar.sync %0, 512;" :: "r"(cbar) : "memory");
            asm volatile("cp.async.wait_group 2;" ::: "memory");

            const int col = tid;
            float zi = s_z[chain][col]        + s_xp[chain][cur][col];
            float zf = s_z[chain][64 + col]   + s_xp[chain][cur][64 + col];
            float zg = s_z[chain][128 + col]  + s_xp[chain][cur][128 + col];
            float zo = s_z[chain][192 + col]  + s_xp[chain][cur][192 + col];
            float c  = sigm_mufu(zf) * s_c[chain][col] + sigm_mufu(zi) * tanh_mufu(zg);
            s_c[chain][col] = c;
            float h  = sigm_mufu(zo) * tanh_mufu(c);
            s_out[chain][cur][col] = h;
            if (t == Tt - 1)
                g_hf[(cl * 2 + chain) * Hh + j * 64 + col] = h;

            asm volatile("bar.sync 3, 64;" ::: "memory");

            if (t < Tt - 1 && tid < 4) {
                asm volatile("fence.proxy.async.shared::cta;" ::: "memory");
                const int p = tid;
                uint32_t src  = s_out_addr + (uint32_t)((chain * 2 + cur) * 256);
                uint32_t ldst = s_h_addr + (uint32_t)(chain * CH_STRIDE + nxt * PAR_STRIDE
                                                      + j * J_STRIDE);
                uint32_t lmb  = mbar_addr + (uint32_t)(chain * 2 + nxt) * 8;
                uint32_t rd, rm;
                asm("mapa.shared::cluster.u32 %0, %1, %2;" : "=r"(rd) : "r"(ldst), "r"(p));
                asm("mapa.shared::cluster.u32 %0, %1, %2;" : "=r"(rm) : "r"(lmb), "r"(p));
                asm volatile(
                    "cp.async.bulk.shared::cluster.shared::cta.mbarrier::complete_tx::bytes "
                    "[%0], [%1], %2, [%3];"
                    :: "r"(rd), "r"(src), "r"(256), "r"(rm) : "memory");
            }
        } else {
            // FMA-only warps: arrive on THIS chain's barrier only.
            // Runahead on each barrier is bounded to 1 phase by the
            // per-chain mbar wait (requires own gates' send of t-1).
            asm volatile("bar.arrive %0, 512;" :: "r"(cbar) : "memory");
        }
    }
}

// =====================================================================
// Kernel 3: backward LSTM (single step, h=c=0) + fc1(relu) + fc2
// =====================================================================
__global__ __launch_bounds__(256) void head_kernel(
    const int* __restrict__ x,
    const float* __restrict__ emb,
    const float* __restrict__ wihb,
    const float* __restrict__ bihb,
    const float* __restrict__ bhhb,
    const float* __restrict__ fc1w,
    const float* __restrict__ fc1b,
    const float* __restrict__ fc2w,
    const float* __restrict__ fc2b,
    float* __restrict__ out)
{
    __shared__ __align__(16) float s_e[Ee];
    __shared__ float s_lo[2 * Hh];
    __shared__ float s_f1[24];

    const int b = blockIdx.x;
    const int tid = threadIdx.x;

    const int tok = x[b * Tt + (Tt - 1)];
    s_e[tid]  = emb[(size_t)tok * Ee + tid];
    s_lo[tid] = g_hf[b * Hh + tid];
    __syncthreads();

    float zi = bihb[tid]       + bhhb[tid];
    float zg = bihb[512 + tid] + bhhb[512 + tid];
    float zo = bihb[768 + tid] + bhhb[768 + tid];
    const float4* wi = (const float4*)(wihb + (size_t)tid * Ee);
    const float4* wg = (const float4*)(wihb + (size_t)(512 + tid) * Ee);
    const float4* wo = (const float4*)(wihb + (size_t)(768 + tid) * Ee);
    const float4* ev = (const float4*)s_e;
#pragma unroll 4
    for (int q = 0; q < Ee / 4; q++) {
        float4 e4 = ev[q];
        float4 vi = wi[q], vg = wg[q], vo = wo[q];
        zi += vi.x * e4.x + vi.y * e4.y + vi.z * e4.z + vi.w * e4.w;
        zg += vg.x * e4.x + vg.y * e4.y + vg.z * e4.z + vg.w * e4.w;
        zo += vo.x * e4.x + vo.y * e4.y + vo.z * e4.z + vo.w * e4.w;
    }
    float c = sigm(zi) * tanhf(zg);   // c_prev = 0: forget gate drops out
    float h = sigm(zo) * tanhf(c);
    s_lo[Hh + tid] = h;
    __syncthreads();

    if (tid < 24) {
        float s = fc1b[tid];
        const float* w = fc1w + (size_t)tid * (2 * Hh);
#pragma unroll 8
        for (int k = 0; k < 2 * Hh; k++) s = fmaf(w[k], s_lo[k], s);
        s_f1[tid] = fmaxf(s, 0.0f);
    }
    __syncthreads();
    if (tid < Oo) {
        float s = fc2b[tid];
        const float* w = fc2w + (size_t)tid * 24;
#pragma unroll
        for (int k = 0; k < 24; k++) s = fmaf(w[k], s_f1[k], s);
        out[b * Oo + tid] = s;
    }
}

// no-op pad launches: aim the ncu capture slot at the lstm kernel
__global__ void pad_kernel() {}

// =====================================================================
// launch
// =====================================================================
extern "C" void kernel_launch(void* const* d_in, const int* in_sizes, int n_in,
                              void* d_out, int out_size)
{
    const int* x           = (const int*)d_in[0];
    const float* emb       = (const float*)d_in[1];
    const float* w_ih_f    = (const float*)d_in[2];
    const float* w_hh_f    = (const float*)d_in[3];
    const float* b_ih_f    = (const float*)d_in[4];
    const float* b_hh_f    = (const float*)d_in[5];
    const float* w_ih_b    = (const float*)d_in[6];
    // d_in[7] = w_hh_b (unused: backward dir is a single step from h=0)
    const float* b_ih_b    = (const float*)d_in[8];
    const float* b_hh_b    = (const float*)d_in[9];
    const float* fc1_w     = (const float*)d_in[10];
    const float* fc1_b     = (const float*)d_in[11];
    const float* fc2_w     = (const float*)d_in[12];
    const float* fc2_b     = (const float*)d_in[13];
    float* out             = (float*)d_out;

    static bool attr_set = false;
    if (!attr_set) {
        cudaFuncSetAttribute(xproj_mma_kernel,
                             cudaFuncAttributeMaxDynamicSharedMemorySize, XSMEM_BYTES);
        attr_set = true;
    }

    dim3 xgrid(Tt * Bb / XBM, G4 / XBN);   // (256, 8)
    xproj_mma_kernel<<<xgrid, 256, XSMEM_BYTES>>>(x, emb, w_ih_f, b_ih_f, b_hh_f);

    pad_kernel<<<1, 32>>>();
    pad_kernel<<<1, 32>>>();

    lstm_fwd_kernel<<<128, 512>>>(w_hh_f);

    head_kernel<<<Bb, 256>>>(x, emb, w_ih_b, b_ih_b, b_hh_b,
                             fc1_w, fc1_b, fc2_w, fc2_b, out);
}

// round 16
// speedup vs baseline: 1.6378x; 1.6378x over previous
#include <cuda_runtime.h>
#include <cuda_bf16.h>
#include <cstdint>

// ---------------- problem constants ----------------
#define Bb   64
#define Tt   512
#define Ee   256
#define Hh   256
#define G4   1024          // 4*H
#define Oo   2

// ---------------- scratch (device globals: no runtime alloc) ----------------
__device__ float g_xproj[(size_t)Tt * Bb * G4];   // [t][b][gate] fp32, 128MB
__device__ float g_hf[Bb * Hh];                   // final forward hidden

__device__ __forceinline__ float sigm(float x) {
    return __fdividef(1.0f, 1.0f + __expf(-x));
}
__device__ __forceinline__ float tanh_mufu(float x) {
    float r;
    asm("tanh.approx.f32 %0, %1;" : "=f"(r) : "f"(x));
    return r;
}
__device__ __forceinline__ float sigm_mufu(float x) {
    return fmaf(tanh_mufu(0.5f * x), 0.5f, 0.5f);
}

// =====================================================================
// Kernel 1: xproj = emb[x] @ W_ih_f^T + bias via mma.sync tf32.
// NEW staging: cp.async.cg direct global->shared, ROW-major with
// pad-36 rows (fragment LDS conflict-free: 36g+c = 4g+c mod 32),
// raw fp32 bits as tf32 (HW truncation). 1 syncthreads / chunk.
// =====================================================================
#define XBM 128
#define XBN 128
#define XBK 32
#define XROW 36                       // floats per staged row (32 + pad)
#define XMAT (XBM * XROW)             // 4608 floats per matrix chunk
#define XBUF (2 * XMAT)               // A+B per buffer = 9216 floats
#define XBIAS_OFF (2 * XBUF)          // 18432 floats
#define XSMEM_BYTES ((XBIAS_OFF + XBN) * 4)   // 74240 B

__device__ __forceinline__ void mma_tf32(
    float& d0, float& d1, float& d2, float& d3,
    uint32_t a0, uint32_t a1, uint32_t a2, uint32_t a3,
    uint32_t b0, uint32_t b1)
{
    asm volatile(
        "mma.sync.aligned.m16n8k8.row.col.f32.tf32.tf32.f32 "
        "{%0,%1,%2,%3}, {%4,%5,%6,%7}, {%8,%9}, {%0,%1,%2,%3};"
        : "+f"(d0), "+f"(d1), "+f"(d2), "+f"(d3)
        : "r"(a0), "r"(a1), "r"(a2), "r"(a3), "r"(b0), "r"(b1));
}

__global__ void __launch_bounds__(256, 2) xproj_mma_kernel(
    const int* __restrict__ x,
    const float* __restrict__ emb,
    const float* __restrict__ wih,
    const float* __restrict__ bih,
    const float* __restrict__ bhh)
{
    extern __shared__ __align__(16) float s[];
    const uint32_t s_u32 = (uint32_t)__cvta_generic_to_shared(s);
    const int tid  = threadIdx.x;
    const int wid  = tid >> 5;
    const int lane = tid & 31;
    const int g    = lane >> 2;
    const int c    = lane & 3;
    const int bm   = blockIdx.x;
    const int bn   = blockIdx.y;
    const int warp_m = (wid >> 1) * 32;
    const int warp_n = (wid & 1) * 64;

    // loader role: row r (0..127), 16-float half kq of the 32-float chunk row
    const int r  = tid >> 1;
    const int kq = tid & 1;
    const int m  = bm * XBM + r;
    const int tok = x[(m & 63) * Tt + (m >> 6)];
    const float* arow = emb + (size_t)tok * Ee;
    const float* brow = wih + (size_t)(bn * XBN + r) * Ee;

    if (tid < XBN)
        s[XBIAS_OFF + tid] = bih[bn * XBN + tid] + bhh[bn * XBN + tid];

    float d[2][8][4];
#pragma unroll
    for (int i = 0; i < 2; i++)
#pragma unroll
        for (int n = 0; n < 8; n++)
#pragma unroll
            for (int e = 0; e < 4; e++) d[i][n][e] = 0.0f;

    // stage chunk ch into buffer buf: 4+4 cp.async of 16B per thread
    auto stage = [&](int ch, int buf) {
        const float* sa = arow + ch * XBK + kq * 16;
        const float* sb = brow + ch * XBK + kq * 16;
        uint32_t da = s_u32 + (uint32_t)(buf * XBUF + r * XROW + kq * 16) * 4u;
        uint32_t db = da + (uint32_t)XMAT * 4u;
#pragma unroll
        for (int i = 0; i < 4; i++) {
            asm volatile("cp.async.cg.shared.global [%0], [%1], 16;"
                         :: "r"(da + i * 16), "l"(sa + i * 4));
            asm volatile("cp.async.cg.shared.global [%0], [%1], 16;"
                         :: "r"(db + i * 16), "l"(sb + i * 4));
        }
        asm volatile("cp.async.commit_group;" ::: "memory");
    };

    stage(0, 0);

    for (int ch = 0; ch < 8; ch++) {
        const int buf = ch & 1;

        asm volatile("cp.async.wait_group 0;" ::: "memory");
        __syncthreads();   // chunk ch visible; all warps done with buffer buf^1

        if (ch < 7) stage(ch + 1, buf ^ 1);

        const uint32_t* As = (const uint32_t*)(s + buf * XBUF);
        const uint32_t* Bs = As + XMAT;
#pragma unroll
        for (int ks = 0; ks < 4; ks++) {
            const int k8 = ks * 8;
            uint32_t a[2][4];
#pragma unroll
            for (int m16 = 0; m16 < 2; m16++) {
                const int rr = warp_m + m16 * 16 + g;
                a[m16][0] = As[rr * XROW + k8 + c];
                a[m16][1] = As[(rr + 8) * XROW + k8 + c];
                a[m16][2] = As[rr * XROW + k8 + c + 4];
                a[m16][3] = As[(rr + 8) * XROW + k8 + c + 4];
            }
            uint32_t b[8][2];
#pragma unroll
            for (int i = 0; i < 8; i++) {
                const int nn = warp_n + i * 8 + g;
                b[i][0] = Bs[nn * XROW + k8 + c];
                b[i][1] = Bs[nn * XROW + k8 + c + 4];
            }
#pragma unroll
            for (int m16 = 0; m16 < 2; m16++)
#pragma unroll
                for (int i = 0; i < 8; i++)
                    mma_tf32(d[m16][i][0], d[m16][i][1], d[m16][i][2], d[m16][i][3],
                             a[m16][0], a[m16][1], a[m16][2], a[m16][3],
                             b[i][0], b[i][1]);
        }
    }

    // epilogue: bias + store
    const float* sbias = s + XBIAS_OFF;
#pragma unroll
    for (int m16 = 0; m16 < 2; m16++) {
        const int row0 = bm * XBM + warp_m + m16 * 16 + g;
#pragma unroll
        for (int i = 0; i < 8; i++) {
            const int col_l = warp_n + i * 8 + 2 * c;
            const float bx = sbias[col_l], by = sbias[col_l + 1];
            float2 v0 = make_float2(d[m16][i][0] + bx, d[m16][i][1] + by);
            float2 v1 = make_float2(d[m16][i][2] + bx, d[m16][i][3] + by);
            *(float2*)(g_xproj + (size_t)row0 * G4 + bn * XBN + col_l) = v0;
            *(float2*)(g_xproj + (size_t)(row0 + 8) * G4 + bn * XBN + col_l) = v1;
        }
    }
}

// =====================================================================
// Kernel 2: forward LSTM — ROUND-13 EXACT (best recurrence: 1359us).
// 32 clusters x 4 CTAs, 512 thr/CTA; CTA owns 64 h-cols (256 gate rows),
// 2 batches/cluster; thread = (row, k-half) -> 64 weight regs.
// Exchange: 4x 512B bulk push + complete_tx; MUFU gates; asym barriers.
// =====================================================================
#define J_STRIDE   544               // bytes per src-CTA h block (512 used + pad)
#define PAR_STRIDE (4 * J_STRIDE)    // 2176

__device__ __forceinline__ void mbar_wait_cluster(uint32_t mbar, uint32_t parity) {
    asm volatile(
        "{\n\t"
        ".reg .pred P;\n\t"
        "WAIT_%=:\n\t"
        "mbarrier.try_wait.parity.acquire.cluster.shared::cta.b64 P, [%0], %1, 0x989680;\n\t"
        "@P bra DONE_%=;\n\t"
        "bra WAIT_%=;\n\t"
        "DONE_%=:\n\t"
        "}"
        :: "r"(mbar), "r"(parity) : "memory");
}

__global__ void __cluster_dims__(4, 1, 1) __launch_bounds__(512, 1)
lstm_fwd_kernel(const float* __restrict__ whh)
{
    __shared__ __align__(16) unsigned char s_h_raw[2 * PAR_STRIDE];
    __shared__ float s_z[2][256];                     // [batch][row]
    __shared__ __align__(16) float s_xp[2][2][256];   // [parity][batch][gate*64+col]
    __shared__ float s_c[2][64];
    __shared__ __align__(16) float s_out[2][2][64];   // [parity][batch][col]
    __shared__ __align__(8) unsigned long long s_mbar[2];

    const int tid  = threadIdx.x;                     // 0..511
    const int j    = blockIdx.x & 3;                  // cluster rank
    const int cl   = blockIdx.x >> 2;                 // batch group (0..31)
    const int row  = tid >> 1;                        // 0..255 (own gate row)
    const int half = tid & 1;                         // k half

    // global gate row: gate = row>>6, col = j*64 + (row&63)
    const int grow = ((row >> 6) << 8) + j * 64 + (row & 63);

    // 128 weights (own half of k) as 64 packed f32x2 regs
    unsigned long long w[64];
    {
        const float* wp = whh + (size_t)grow * Hh + half * 128;
#pragma unroll
        for (int q = 0; q < 32; q++) {
            ulonglong2 v = *(const ulonglong2*)(wp + q * 4);
            w[2*q] = v.x; w[2*q+1] = v.y;
        }
    }

    // init
    for (int i = tid; i < 2 * PAR_STRIDE / 4; i += 512) ((float*)s_h_raw)[i] = 0.0f;
    if (tid < 128) s_c[tid >> 6][tid & 63] = 0.0f;

    const uint32_t s_h_addr   = (uint32_t)__cvta_generic_to_shared(&s_h_raw[0]);
    const uint32_t s_xp_addr  = (uint32_t)__cvta_generic_to_shared(&s_xp[0][0][0]);
    const uint32_t s_out_addr = (uint32_t)__cvta_generic_to_shared(&s_out[0][0][0]);
    const uint32_t mbar_addr  = (uint32_t)__cvta_generic_to_shared(&s_mbar[0]);

    if (tid == 0) {
        asm volatile("mbarrier.init.shared.b64 [%0], 1;" :: "r"(mbar_addr) : "memory");
        asm volatile("mbarrier.init.shared.b64 [%0], 1;" :: "r"(mbar_addr + 8) : "memory");
    }

    // prefetch xproj slice for t=0 into parity 0 (128 threads x 16B)
    if (tid < 128) {
        int bl = tid >> 6, u = tid & 63;
        int gate = u >> 4, col4 = (u & 15) * 4;
        const float* src = g_xproj + ((size_t)0 * Bb + cl * 2 + bl) * G4
                           + gate * 256 + j * 64 + col4;
        uint32_t dst = s_xp_addr + (uint32_t)((bl * 256) + u * 4) * 4u;
        asm volatile("cp.async.ca.shared.global [%0], [%1], 16;" :: "r"(dst), "l"(src));
        asm volatile("cp.async.commit_group;" ::: "memory");
    }

    __syncthreads();
    asm volatile("barrier.cluster.arrive.aligned;" ::: "memory");
    asm volatile("barrier.cluster.wait.aligned;"   ::: "memory");

    for (int t = 0; t < Tt; t++) {
        const int cur = t & 1, nxt = cur ^ 1;

        if (t > 0) {
            int ph = (t & 1) ? ((t >> 1) & 1) : (((t >> 1) + 1) & 1);
            mbar_wait_cluster(mbar_addr + (uint32_t)cur * 8, (uint32_t)ph);
        }
        if (t < Tt - 1 && tid == 0) {
            asm volatile("mbarrier.arrive.expect_tx.shared.b64 _, [%0], %1;"
                         :: "r"(mbar_addr + (uint32_t)nxt * 8), "r"(2048) : "memory");
        }

        // prefetch next step's xproj slice (gate warps only)
        if (tid < 128) {
            int tn = (t + 1 < Tt) ? t + 1 : (Tt - 1);
            int bl = tid >> 6, u = tid & 63;
            int gate = u >> 4, col4 = (u & 15) * 4;
            const float* src = g_xproj + ((size_t)tn * Bb + cl * 2 + bl) * G4
                               + gate * 256 + j * 64 + col4;
            uint32_t dst = s_xp_addr + (uint32_t)(((nxt * 2 + bl) * 256) + u * 4) * 4u;
            asm volatile("cp.async.ca.shared.global [%0], [%1], 16;" :: "r"(dst), "l"(src));
            asm volatile("cp.async.commit_group;" ::: "memory");
        }

        // ---- Whh @ h: thread = (row, k-half), 2 batches ----
        unsigned long long acc[2] = {0, 0};
        const unsigned char* hb = s_h_raw + cur * PAR_STRIDE + (half * 2) * J_STRIDE;
#pragma unroll
        for (int sblk = 0; sblk < 2; sblk++) {
#pragma unroll
            for (int q = 0; q < 16; q++) {
                const unsigned char* hq = hb + sblk * J_STRIDE + q * 16;
#pragma unroll
                for (int bl = 0; bl < 2; bl++) {
                    ulonglong2 h2 = *(const ulonglong2*)(hq + bl * 256);
                    int wi = 2 * (sblk * 16 + q);
                    asm("fma.rn.f32x2 %0, %1, %2, %0;" : "+l"(acc[bl]) : "l"(w[wi]),   "l"(h2.x));
                    asm("fma.rn.f32x2 %0, %1, %2, %0;" : "+l"(acc[bl]) : "l"(w[wi+1]), "l"(h2.y));
                }
            }
        }
        float f[2];
#pragma unroll
        for (int bl = 0; bl < 2; bl++) {
            f[bl] = __uint_as_float((unsigned)acc[bl]) + __uint_as_float((unsigned)(acc[bl] >> 32));
            f[bl] += __shfl_xor_sync(0xffffffffu, f[bl], 1);
        }
        if (half == 0) {
#pragma unroll
            for (int bl = 0; bl < 2; bl++) s_z[bl][row] = f[bl];
        }

        if (tid < 128) {
            asm volatile("bar.sync 1, 512;" ::: "memory");
            asm volatile("cp.async.wait_group 1;" ::: "memory");

            const int bl = tid >> 6, col = tid & 63;
            float zi = s_z[bl][col]        + s_xp[cur][bl][col];
            float zf = s_z[bl][64 + col]   + s_xp[cur][bl][64 + col];
            float zg = s_z[bl][128 + col]  + s_xp[cur][bl][128 + col];
            float zo = s_z[bl][192 + col]  + s_xp[cur][bl][192 + col];
            float c  = sigm_mufu(zf) * s_c[bl][col] + sigm_mufu(zi) * tanh_mufu(zg);
            s_c[bl][col] = c;
            float h  = sigm_mufu(zo) * tanh_mufu(c);
            s_out[cur][bl][col] = h;
            if (t == Tt - 1)
                g_hf[(cl * 2 + bl) * Hh + j * 64 + col] = h;

            asm volatile("bar.sync 2, 128;" ::: "memory");

            if (t < Tt - 1 && tid < 4) {
                asm volatile("fence.proxy.async.shared::cta;" ::: "memory");
                const int p = tid;
                uint32_t src  = s_out_addr + (uint32_t)(cur * 512);
                uint32_t ldst = s_h_addr + (uint32_t)(nxt * PAR_STRIDE + j * J_STRIDE);
                uint32_t lmb  = mbar_addr + (uint32_t)nxt * 8;
                uint32_t rd, rm;
                asm("mapa.shared::cluster.u32 %0, %1, %2;" : "=r"(rd) : "r"(ldst), "r"(p));
                asm("mapa.shared::cluster.u32 %0, %1, %2;" : "=r"(rm) : "r"(lmb), "r"(p));
                asm volatile(
                    "cp.async.bulk.shared::cluster.shared::cta.mbarrier::complete_tx::bytes "
                    "[%0], [%1], %2, [%3];"
                    :: "r"(rd), "r"(src), "r"(512), "r"(rm) : "memory");
            }
        } else {
            // FMA-only warps: signal s_z done, go straight to next wait.
            asm volatile("bar.arrive 1, 512;" ::: "memory");
        }
    }
}

// =====================================================================
// Kernel 3: backward LSTM (single step, h=c=0) + fc1(relu) + fc2
// =====================================================================
__global__ __launch_bounds__(256) void head_kernel(
    const int* __restrict__ x,
    const float* __restrict__ emb,
    const float* __restrict__ wihb,
    const float* __restrict__ bihb,
    const float* __restrict__ bhhb,
    const float* __restrict__ fc1w,
    const float* __restrict__ fc1b,
    const float* __restrict__ fc2w,
    const float* __restrict__ fc2b,
    float* __restrict__ out)
{
    __shared__ __align__(16) float s_e[Ee];
    __shared__ float s_lo[2 * Hh];
    __shared__ float s_f1[24];

    const int b = blockIdx.x;
    const int tid = threadIdx.x;

    const int tok = x[b * Tt + (Tt - 1)];
    s_e[tid]  = emb[(size_t)tok * Ee + tid];
    s_lo[tid] = g_hf[b * Hh + tid];
    __syncthreads();

    float zi = bihb[tid]       + bhhb[tid];
    float zg = bihb[512 + tid] + bhhb[512 + tid];
    float zo = bihb[768 + tid] + bhhb[768 + tid];
    const float4* wi = (const float4*)(wihb + (size_t)tid * Ee);
    const float4* wg = (const float4*)(wihb + (size_t)(512 + tid) * Ee);
    const float4* wo = (const float4*)(wihb + (size_t)(768 + tid) * Ee);
    const float4* ev = (const float4*)s_e;
#pragma unroll 4
    for (int q = 0; q < Ee / 4; q++) {
        float4 e4 = ev[q];
        float4 vi = wi[q], vg = wg[q], vo = wo[q];
        zi += vi.x * e4.x + vi.y * e4.y + vi.z * e4.z + vi.w * e4.w;
        zg += vg.x * e4.x + vg.y * e4.y + vg.z * e4.z + vg.w * e4.w;
        zo += vo.x * e4.x + vo.y * e4.y + vo.z * e4.z + vo.w * e4.w;
    }
    float c = sigm(zi) * tanhf(zg);   // c_prev = 0: forget gate drops out
    float h = sigm(zo) * tanhf(c);
    s_lo[Hh + tid] = h;
    __syncthreads();

    if (tid < 24) {
        float s = fc1b[tid];
        const float* w = fc1w + (size_t)tid * (2 * Hh);
#pragma unroll 8
        for (int k = 0; k < 2 * Hh; k++) s = fmaf(w[k], s_lo[k], s);
        s_f1[tid] = fmaxf(s, 0.0f);
    }
    __syncthreads();
    if (tid < Oo) {
        float s = fc2b[tid];
        const float* w = fc2w + (size_t)tid * 24;
#pragma unroll
        for (int k = 0; k < 24; k++) s = fmaf(w[k], s_f1[k], s);
        out[b * Oo + tid] = s;
    }
}

// no-op pad launches: aim the ncu capture slot at the lstm kernel
__global__ void pad_kernel() {}

// =====================================================================
// launch
// =====================================================================
extern "C" void kernel_launch(void* const* d_in, const int* in_sizes, int n_in,
                              void* d_out, int out_size)
{
    const int* x           = (const int*)d_in[0];
    const float* emb       = (const float*)d_in[1];
    const float* w_ih_f    = (const float*)d_in[2];
    const float* w_hh_f    = (const float*)d_in[3];
    const float* b_ih_f    = (const float*)d_in[4];
    const float* b_hh_f    = (const float*)d_in[5];
    const float* w_ih_b    = (const float*)d_in[6];
    // d_in[7] = w_hh_b (unused: backward dir is a single step from h=0)
    const float* b_ih_b    = (const float*)d_in[8];
    const float* b_hh_b    = (const float*)d_in[9];
    const float* fc1_w     = (const float*)d_in[10];
    const float* fc1_b     = (const float*)d_in[11];
    const float* fc2_w     = (const float*)d_in[12];
    const float* fc2_b     = (const float*)d_in[13];
    float* out             = (float*)d_out;

    static bool attr_set = false;
    if (!attr_set) {
        cudaFuncSetAttribute(xproj_mma_kernel,
                             cudaFuncAttributeMaxDynamicSharedMemorySize, XSMEM_BYTES);
        attr_set = true;
    }

    dim3 xgrid(Tt * Bb / XBM, G4 / XBN);   // (256, 8)
    xproj_mma_kernel<<<xgrid, 256, XSMEM_BYTES>>>(x, emb, w_ih_f, b_ih_f, b_hh_f);

    pad_kernel<<<1, 32>>>();
    pad_kernel<<<1, 32>>>();

    lstm_fwd_kernel<<<128, 512>>>(w_hh_f);

    head_kernel<<<Bb, 256>>>(x, emb, w_ih_b, b_ih_b, b_hh_b,
                             fc1_w, fc1_b, fc2_w, fc2_b, out);
}

// round 17
// speedup vs baseline: 1.6434x; 1.0034x over previous
#include <cuda_runtime.h>
#include <cuda_bf16.h>
#include <cstdint>

// ---------------- problem constants ----------------
#define Bb   64
#define Tt   512
#define Ee   256
#define Hh   256
#define G4   1024          // 4*H
#define Oo   2

// ---------------- scratch (device globals: no runtime alloc) ----------------
__device__ float g_xproj[(size_t)Tt * Bb * G4];   // [t][b][gate] fp32, 128MB
__device__ float g_hf[Bb * Hh];                   // final forward hidden

__device__ __forceinline__ float sigm(float x) {
    return __fdividef(1.0f, 1.0f + __expf(-x));
}
__device__ __forceinline__ float tanh_mufu(float x) {
    float r;
    asm("tanh.approx.f32 %0, %1;" : "=f"(r) : "f"(x));
    return r;
}
__device__ __forceinline__ float sigm_mufu(float x) {
    return fmaf(tanh_mufu(0.5f * x), 0.5f, 0.5f);
}

// =====================================================================
// Kernel 1: xproj = emb[x] @ W_ih_f^T + bias via mma.sync tf32.
// cp.async row-major staging (pad-36), THREE-buffer pipeline:
// wait_group 1 keeps one chunk in flight under the MMAs.
// =====================================================================
#define XBM 128
#define XBN 128
#define XBK 32
#define XROW 36                       // floats per staged row (32 + pad)
#define XMAT (XBM * XROW)             // 4608 floats per matrix chunk
#define XBUF (2 * XMAT)               // A+B per buffer = 9216 floats
#define XNBUF 3
#define XBIAS_OFF (XNBUF * XBUF)      // 27648 floats
#define XSMEM_BYTES ((XBIAS_OFF + XBN) * 4)   // 111104 B

__device__ __forceinline__ void mma_tf32(
    float& d0, float& d1, float& d2, float& d3,
    uint32_t a0, uint32_t a1, uint32_t a2, uint32_t a3,
    uint32_t b0, uint32_t b1)
{
    asm volatile(
        "mma.sync.aligned.m16n8k8.row.col.f32.tf32.tf32.f32 "
        "{%0,%1,%2,%3}, {%4,%5,%6,%7}, {%8,%9}, {%0,%1,%2,%3};"
        : "+f"(d0), "+f"(d1), "+f"(d2), "+f"(d3)
        : "r"(a0), "r"(a1), "r"(a2), "r"(a3), "r"(b0), "r"(b1));
}

__global__ void __launch_bounds__(256, 2) xproj_mma_kernel(
    const int* __restrict__ x,
    const float* __restrict__ emb,
    const float* __restrict__ wih,
    const float* __restrict__ bih,
    const float* __restrict__ bhh)
{
    extern __shared__ __align__(16) float s[];
    const uint32_t s_u32 = (uint32_t)__cvta_generic_to_shared(s);
    const int tid  = threadIdx.x;
    const int wid  = tid >> 5;
    const int lane = tid & 31;
    const int g    = lane >> 2;
    const int c    = lane & 3;
    const int bm   = blockIdx.x;
    const int bn   = blockIdx.y;
    const int warp_m = (wid >> 1) * 32;
    const int warp_n = (wid & 1) * 64;

    // loader role: row r (0..127), 16-float half kq of the 32-float chunk row
    const int r  = tid >> 1;
    const int kq = tid & 1;
    const int m  = bm * XBM + r;
    const int tok = x[(m & 63) * Tt + (m >> 6)];
    const float* arow = emb + (size_t)tok * Ee;
    const float* brow = wih + (size_t)(bn * XBN + r) * Ee;

    if (tid < XBN)
        s[XBIAS_OFF + tid] = bih[bn * XBN + tid] + bhh[bn * XBN + tid];

    float d[2][8][4];
#pragma unroll
    for (int i = 0; i < 2; i++)
#pragma unroll
        for (int n = 0; n < 8; n++)
#pragma unroll
            for (int e = 0; e < 4; e++) d[i][n][e] = 0.0f;

    // stage chunk ch into buffer buf: 4+4 cp.async of 16B per thread
    auto stage = [&](int ch, int buf) {
        const float* sa = arow + ch * XBK + kq * 16;
        const float* sb = brow + ch * XBK + kq * 16;
        uint32_t da = s_u32 + (uint32_t)(buf * XBUF + r * XROW + kq * 16) * 4u;
        uint32_t db = da + (uint32_t)XMAT * 4u;
#pragma unroll
        for (int i = 0; i < 4; i++) {
            asm volatile("cp.async.cg.shared.global [%0], [%1], 16;"
                         :: "r"(da + i * 16), "l"(sa + i * 4));
            asm volatile("cp.async.cg.shared.global [%0], [%1], 16;"
                         :: "r"(db + i * 16), "l"(sb + i * 4));
        }
        asm volatile("cp.async.commit_group;" ::: "memory");
    };

    stage(0, 0);
    stage(1, 1);

    int buf = 0;
    for (int ch = 0; ch < 8; ch++) {
        if (ch < 7) {
            asm volatile("cp.async.wait_group 1;" ::: "memory");
        } else {
            asm volatile("cp.async.wait_group 0;" ::: "memory");
        }
        __syncthreads();   // chunk ch visible in buf; buffer (buf+2)%3 free

        if (ch < 6) {
            int nb = buf + 2; if (nb >= XNBUF) nb -= XNBUF;
            stage(ch + 2, nb);
        }

        const uint32_t* As = (const uint32_t*)(s + buf * XBUF);
        const uint32_t* Bs = As + XMAT;
#pragma unroll
        for (int ks = 0; ks < 4; ks++) {
            const int k8 = ks * 8;
            uint32_t a[2][4];
#pragma unroll
            for (int m16 = 0; m16 < 2; m16++) {
                const int rr = warp_m + m16 * 16 + g;
                a[m16][0] = As[rr * XROW + k8 + c];
                a[m16][1] = As[(rr + 8) * XROW + k8 + c];
                a[m16][2] = As[rr * XROW + k8 + c + 4];
                a[m16][3] = As[(rr + 8) * XROW + k8 + c + 4];
            }
            uint32_t b[8][2];
#pragma unroll
            for (int i = 0; i < 8; i++) {
                const int nn = warp_n + i * 8 + g;
                b[i][0] = Bs[nn * XROW + k8 + c];
                b[i][1] = Bs[nn * XROW + k8 + c + 4];
            }
#pragma unroll
            for (int m16 = 0; m16 < 2; m16++)
#pragma unroll
                for (int i = 0; i < 8; i++)
                    mma_tf32(d[m16][i][0], d[m16][i][1], d[m16][i][2], d[m16][i][3],
                             a[m16][0], a[m16][1], a[m16][2], a[m16][3],
                             b[i][0], b[i][1]);
        }

        if (++buf >= XNBUF) buf = 0;
    }

    // epilogue: bias + store
    const float* sbias = s + XBIAS_OFF;
#pragma unroll
    for (int m16 = 0; m16 < 2; m16++) {
        const int row0 = bm * XBM + warp_m + m16 * 16 + g;
#pragma unroll
        for (int i = 0; i < 8; i++) {
            const int col_l = warp_n + i * 8 + 2 * c;
            const float bx = sbias[col_l], by = sbias[col_l + 1];
            float2 v0 = make_float2(d[m16][i][0] + bx, d[m16][i][1] + by);
            float2 v1 = make_float2(d[m16][i][2] + bx, d[m16][i][3] + by);
            *(float2*)(g_xproj + (size_t)row0 * G4 + bn * XBN + col_l) = v0;
            *(float2*)(g_xproj + (size_t)(row0 + 8) * G4 + bn * XBN + col_l) = v1;
        }
    }
}

// =====================================================================
// Kernel 2: forward LSTM — ROUND-13 EXACT (best recurrence: 1359us).
// =====================================================================
#define J_STRIDE   544               // bytes per src-CTA h block (512 used + pad)
#define PAR_STRIDE (4 * J_STRIDE)    // 2176

__device__ __forceinline__ void mbar_wait_cluster(uint32_t mbar, uint32_t parity) {
    asm volatile(
        "{\n\t"
        ".reg .pred P;\n\t"
        "WAIT_%=:\n\t"
        "mbarrier.try_wait.parity.acquire.cluster.shared::cta.b64 P, [%0], %1, 0x989680;\n\t"
        "@P bra DONE_%=;\n\t"
        "bra WAIT_%=;\n\t"
        "DONE_%=:\n\t"
        "}"
        :: "r"(mbar), "r"(parity) : "memory");
}

__global__ void __cluster_dims__(4, 1, 1) __launch_bounds__(512, 1)
lstm_fwd_kernel(const float* __restrict__ whh)
{
    __shared__ __align__(16) unsigned char s_h_raw[2 * PAR_STRIDE];
    __shared__ float s_z[2][256];                     // [batch][row]
    __shared__ __align__(16) float s_xp[2][2][256];   // [parity][batch][gate*64+col]
    __shared__ float s_c[2][64];
    __shared__ __align__(16) float s_out[2][2][64];   // [parity][batch][col]
    __shared__ __align__(8) unsigned long long s_mbar[2];

    const int tid  = threadIdx.x;                     // 0..511
    const int j    = blockIdx.x & 3;                  // cluster rank
    const int cl   = blockIdx.x >> 2;                 // batch group (0..31)
    const int row  = tid >> 1;                        // 0..255 (own gate row)
    const int half = tid & 1;                         // k half

    // global gate row: gate = row>>6, col = j*64 + (row&63)
    const int grow = ((row >> 6) << 8) + j * 64 + (row & 63);

    // 128 weights (own half of k) as 64 packed f32x2 regs
    unsigned long long w[64];
    {
        const float* wp = whh + (size_t)grow * Hh + half * 128;
#pragma unroll
        for (int q = 0; q < 32; q++) {
            ulonglong2 v = *(const ulonglong2*)(wp + q * 4);
            w[2*q] = v.x; w[2*q+1] = v.y;
        }
    }

    // init
    for (int i = tid; i < 2 * PAR_STRIDE / 4; i += 512) ((float*)s_h_raw)[i] = 0.0f;
    if (tid < 128) s_c[tid >> 6][tid & 63] = 0.0f;

    const uint32_t s_h_addr   = (uint32_t)__cvta_generic_to_shared(&s_h_raw[0]);
    const uint32_t s_xp_addr  = (uint32_t)__cvta_generic_to_shared(&s_xp[0][0][0]);
    const uint32_t s_out_addr = (uint32_t)__cvta_generic_to_shared(&s_out[0][0][0]);
    const uint32_t mbar_addr  = (uint32_t)__cvta_generic_to_shared(&s_mbar[0]);

    if (tid == 0) {
        asm volatile("mbarrier.init.shared.b64 [%0], 1;" :: "r"(mbar_addr) : "memory");
        asm volatile("mbarrier.init.shared.b64 [%0], 1;" :: "r"(mbar_addr + 8) : "memory");
    }

    // prefetch xproj slice for t=0 into parity 0 (128 threads x 16B)
    if (tid < 128) {
        int bl = tid >> 6, u = tid & 63;
        int gate = u >> 4, col4 = (u & 15) * 4;
        const float* src = g_xproj + ((size_t)0 * Bb + cl * 2 + bl) * G4
                           + gate * 256 + j * 64 + col4;
        uint32_t dst = s_xp_addr + (uint32_t)((bl * 256) + u * 4) * 4u;
        asm volatile("cp.async.ca.shared.global [%0], [%1], 16;" :: "r"(dst), "l"(src));
        asm volatile("cp.async.commit_group;" ::: "memory");
    }

    __syncthreads();
    asm volatile("barrier.cluster.arrive.aligned;" ::: "memory");
    asm volatile("barrier.cluster.wait.aligned;"   ::: "memory");

    for (int t = 0; t < Tt; t++) {
        const int cur = t & 1, nxt = cur ^ 1;

        if (t > 0) {
            int ph = (t & 1) ? ((t >> 1) & 1) : (((t >> 1) + 1) & 1);
            mbar_wait_cluster(mbar_addr + (uint32_t)cur * 8, (uint32_t)ph);
        }
        if (t < Tt - 1 && tid == 0) {
            asm volatile("mbarrier.arrive.expect_tx.shared.b64 _, [%0], %1;"
                         :: "r"(mbar_addr + (uint32_t)nxt * 8), "r"(2048) : "memory");
        }

        // prefetch next step's xproj slice (gate warps only)
        if (tid < 128) {
            int tn = (t + 1 < Tt) ? t + 1 : (Tt - 1);
            int bl = tid >> 6, u = tid & 63;
            int gate = u >> 4, col4 = (u & 15) * 4;
            const float* src = g_xproj + ((size_t)tn * Bb + cl * 2 + bl) * G4
                               + gate * 256 + j * 64 + col4;
            uint32_t dst = s_xp_addr + (uint32_t)(((nxt * 2 + bl) * 256) + u * 4) * 4u;
            asm volatile("cp.async.ca.shared.global [%0], [%1], 16;" :: "r"(dst), "l"(src));
            asm volatile("cp.async.commit_group;" ::: "memory");
        }

        // ---- Whh @ h: thread = (row, k-half), 2 batches ----
        unsigned long long acc[2] = {0, 0};
        const unsigned char* hb = s_h_raw + cur * PAR_STRIDE + (half * 2) * J_STRIDE;
#pragma unroll
        for (int sblk = 0; sblk < 2; sblk++) {
#pragma unroll
            for (int q = 0; q < 16; q++) {
                const unsigned char* hq = hb + sblk * J_STRIDE + q * 16;
#pragma unroll
                for (int bl = 0; bl < 2; bl++) {
                    ulonglong2 h2 = *(const ulonglong2*)(hq + bl * 256);
                    int wi = 2 * (sblk * 16 + q);
                    asm("fma.rn.f32x2 %0, %1, %2, %0;" : "+l"(acc[bl]) : "l"(w[wi]),   "l"(h2.x));
                    asm("fma.rn.f32x2 %0, %1, %2, %0;" : "+l"(acc[bl]) : "l"(w[wi+1]), "l"(h2.y));
                }
            }
        }
        float f[2];
#pragma unroll
        for (int bl = 0; bl < 2; bl++) {
            f[bl] = __uint_as_float((unsigned)acc[bl]) + __uint_as_float((unsigned)(acc[bl] >> 32));
            f[bl] += __shfl_xor_sync(0xffffffffu, f[bl], 1);
        }
        if (half == 0) {
#pragma unroll
            for (int bl = 0; bl < 2; bl++) s_z[bl][row] = f[bl];
        }

        if (tid < 128) {
            asm volatile("bar.sync 1, 512;" ::: "memory");
            asm volatile("cp.async.wait_group 1;" ::: "memory");

            const int bl = tid >> 6, col = tid & 63;
            float zi = s_z[bl][col]        + s_xp[cur][bl][col];
            float zf = s_z[bl][64 + col]   + s_xp[cur][bl][64 + col];
            float zg = s_z[bl][128 + col]  + s_xp[cur][bl][128 + col];
            float zo = s_z[bl][192 + col]  + s_xp[cur][bl][192 + col];
            float c  = sigm_mufu(zf) * s_c[bl][col] + sigm_mufu(zi) * tanh_mufu(zg);
            s_c[bl][col] = c;
            float h  = sigm_mufu(zo) * tanh_mufu(c);
            s_out[cur][bl][col] = h;
            if (t == Tt - 1)
                g_hf[(cl * 2 + bl) * Hh + j * 64 + col] = h;

            asm volatile("bar.sync 2, 128;" ::: "memory");

            if (t < Tt - 1 && tid < 4) {
                asm volatile("fence.proxy.async.shared::cta;" ::: "memory");
                const int p = tid;
                uint32_t src  = s_out_addr + (uint32_t)(cur * 512);
                uint32_t ldst = s_h_addr + (uint32_t)(nxt * PAR_STRIDE + j * J_STRIDE);
                uint32_t lmb  = mbar_addr + (uint32_t)nxt * 8;
                uint32_t rd, rm;
                asm("mapa.shared::cluster.u32 %0, %1, %2;" : "=r"(rd) : "r"(ldst), "r"(p));
                asm("mapa.shared::cluster.u32 %0, %1, %2;" : "=r"(rm) : "r"(lmb), "r"(p));
                asm volatile(
                    "cp.async.bulk.shared::cluster.shared::cta.mbarrier::complete_tx::bytes "
                    "[%0], [%1], %2, [%3];"
                    :: "r"(rd), "r"(src), "r"(512), "r"(rm) : "memory");
            }
        } else {
            // FMA-only warps: signal s_z done, go straight to next wait.
            asm volatile("bar.arrive 1, 512;" ::: "memory");
        }
    }
}

// =====================================================================
// Kernel 3: backward LSTM (single step, h=c=0) + fc1(relu) + fc2
// =====================================================================
__global__ __launch_bounds__(256) void head_kernel(
    const int* __restrict__ x,
    const float* __restrict__ emb,
    const float* __restrict__ wihb,
    const float* __restrict__ bihb,
    const float* __restrict__ bhhb,
    const float* __restrict__ fc1w,
    const float* __restrict__ fc1b,
    const float* __restrict__ fc2w,
    const float* __restrict__ fc2b,
    float* __restrict__ out)
{
    __shared__ __align__(16) float s_e[Ee];
    __shared__ float s_lo[2 * Hh];
    __shared__ float s_f1[24];

    const int b = blockIdx.x;
    const int tid = threadIdx.x;

    const int tok = x[b * Tt + (Tt - 1)];
    s_e[tid]  = emb[(size_t)tok * Ee + tid];
    s_lo[tid] = g_hf[b * Hh + tid];
    __syncthreads();

    float zi = bihb[tid]       + bhhb[tid];
    float zg = bihb[512 + tid] + bhhb[512 + tid];
    float zo = bihb[768 + tid] + bhhb[768 + tid];
    const float4* wi = (const float4*)(wihb + (size_t)tid * Ee);
    const float4* wg = (const float4*)(wihb + (size_t)(512 + tid) * Ee);
    const float4* wo = (const float4*)(wihb + (size_t)(768 + tid) * Ee);
    const float4* ev = (const float4*)s_e;
#pragma unroll 4
    for (int q = 0; q < Ee / 4; q++) {
        float4 e4 = ev[q];
        float4 vi = wi[q], vg = wg[q], vo = wo[q];
        zi += vi.x * e4.x + vi.y * e4.y + vi.z * e4.z + vi.w * e4.w;
        zg += vg.x * e4.x + vg.y * e4.y + vg.z * e4.z + vg.w * e4.w;
        zo += vo.x * e4.x + vo.y * e4.y + vo.z * e4.z + vo.w * e4.w;
    }
    float c = sigm(zi) * tanhf(zg);   // c_prev = 0: forget gate drops out
    float h = sigm(zo) * tanhf(c);
    s_lo[Hh + tid] = h;
    __syncthreads();

    if (tid < 24) {
        float s = fc1b[tid];
        const float* w = fc1w + (size_t)tid * (2 * Hh);
#pragma unroll 8
        for (int k = 0; k < 2 * Hh; k++) s = fmaf(w[k], s_lo[k], s);
        s_f1[tid] = fmaxf(s, 0.0f);
    }
    __syncthreads();
    if (tid < Oo) {
        float s = fc2b[tid];
        const float* w = fc2w + (size_t)tid * 24;
#pragma unroll
        for (int k = 0; k < 24; k++) s = fmaf(w[k], s_f1[k], s);
        out[b * Oo + tid] = s;
    }
}

// no-op pad launches: aim the ncu capture slot at the lstm kernel
__global__ void pad_kernel() {}

// =====================================================================
// launch
// =====================================================================
extern "C" void kernel_launch(void* const* d_in, const int* in_sizes, int n_in,
                              void* d_out, int out_size)
{
    const int* x           = (const int*)d_in[0];
    const float* emb       = (const float*)d_in[1];
    const float* w_ih_f    = (const float*)d_in[2];
    const float* w_hh_f    = (const float*)d_in[3];
    const float* b_ih_f    = (const float*)d_in[4];
    const float* b_hh_f    = (const float*)d_in[5];
    const float* w_ih_b    = (const float*)d_in[6];
    // d_in[7] = w_hh_b (unused: backward dir is a single step from h=0)
    const float* b_ih_b    = (const float*)d_in[8];
    const float* b_hh_b    = (const float*)d_in[9];
    const float* fc1_w     = (const float*)d_in[10];
    const float* fc1_b     = (const float*)d_in[11];
    const float* fc2_w     = (const float*)d_in[12];
    const float* fc2_b     = (const float*)d_in[13];
    float* out             = (float*)d_out;

    static bool attr_set = false;
    if (!attr_set) {
        cudaFuncSetAttribute(xproj_mma_kernel,
                             cudaFuncAttributeMaxDynamicSharedMemorySize, XSMEM_BYTES);
        attr_set = true;
    }

    dim3 xgrid(Tt * Bb / XBM, G4 / XBN);   // (256, 8)
    xproj_mma_kernel<<<xgrid, 256, XSMEM_BYTES>>>(x, emb, w_ih_f, b_ih_f, b_hh_f);

    pad_kernel<<<1, 32>>>();
    pad_kernel<<<1, 32>>>();

    lstm_fwd_kernel<<<128, 512>>>(w_hh_f);

    head_kernel<<<Bb, 256>>>(x, emb, w_ih_b, b_ih_b, b_hh_b,
                             fc1_w, fc1_b, fc2_w, fc2_b, out);
}